// round 2
// baseline (speedup 1.0000x reference)
#include <cuda_runtime.h>
#include <cuda_bf16.h>

// Fast Walsh-Hadamard transform, 16384 rows x 1024 fp32.
// y[row] = FWHT(x[row]) / 32, emitted as interleaved (real, 0) pairs.
//
// Per row: 128 threads, 8 contiguous elements/thread.
//   strides 1,2,4      -> register butterflies
//   strides 8..128     -> warp shuffle butterflies
//   strides 256,512    -> one smem transpose, then register butterflies
// DEPTH=2 rows per block processed in an interleaved fashion: doubles the
// loads in flight per warp (MLP 2->4) and amortizes the single barrier over
// two rows. 128-thread blocks so the barrier never couples unrelated rows.

#define DIMN  1024
#define TPR   128
#define DEPTH 2

__device__ __forceinline__ void bf(float &x, float &y) {
    float s = x + y;
    y = x - y;
    x = s;
}

__global__ void __launch_bounds__(TPR, 12)
fwht_kernel(const float4* __restrict__ xin, float4* __restrict__ yout, int nrows)
{
    __shared__ float sm[DEPTH][DIMN];
    const int t  = threadIdx.x;
    const int r0 = blockIdx.x * DEPTH;

    float v[DEPTH][8];

    // ---- loads first: 4 independent LDG.128 in flight ----
    #pragma unroll
    for (int d = 0; d < DEPTH; d++) {
        if (r0 + d < nrows) {
            const float4* base = xin + (size_t)(r0 + d) * (DIMN / 4);
            float4 p0 = base[2 * t];
            float4 p1 = base[2 * t + 1];
            v[d][0] = p0.x; v[d][1] = p0.y; v[d][2] = p0.z; v[d][3] = p0.w;
            v[d][4] = p1.x; v[d][5] = p1.y; v[d][6] = p1.z; v[d][7] = p1.w;
        } else {
            #pragma unroll
            for (int j = 0; j < 8; j++) v[d][j] = 0.0f;
        }
    }

    // ---- strides 1,2,4 (register-local; element idx = 8t + j) ----
    #pragma unroll
    for (int d = 0; d < DEPTH; d++) {
        bf(v[d][0], v[d][1]); bf(v[d][2], v[d][3]); bf(v[d][4], v[d][5]); bf(v[d][6], v[d][7]);
        bf(v[d][0], v[d][2]); bf(v[d][1], v[d][3]); bf(v[d][4], v[d][6]); bf(v[d][5], v[d][7]);
        bf(v[d][0], v[d][4]); bf(v[d][1], v[d][5]); bf(v[d][2], v[d][6]); bf(v[d][3], v[d][7]);
    }

    // ---- strides 8..128 via shfl.xor; both rows interleaved for ILP ----
    #pragma unroll
    for (int s = 1; s <= 16; s <<= 1) {
        const bool upper = (t & s) != 0;
        #pragma unroll
        for (int d = 0; d < DEPTH; d++) {
            #pragma unroll
            for (int j = 0; j < 8; j++) {
                float o = __shfl_xor_sync(0xffffffffu, v[d][j], s);
                v[d][j] = upper ? (o - v[d][j]) : (v[d][j] + o);
            }
        }
    }

    // ---- smem transpose: re-gather so strides 256/512 are register-local ----
    #pragma unroll
    for (int d = 0; d < DEPTH; d++) {
        float4* smw = reinterpret_cast<float4*>(&sm[d][8 * t]);
        smw[0] = make_float4(v[d][0], v[d][1], v[d][2], v[d][3]);
        smw[1] = make_float4(v[d][4], v[d][5], v[d][6], v[d][7]);
    }
    __syncthreads();

    const float s = 0.03125f;  // 1/sqrt(1024)
    #pragma unroll
    for (int d = 0; d < DEPTH; d++) {
        // thread t takes elements {2t, 2t+1} + 256k for k=0..3
        const float2* smr = reinterpret_cast<const float2*>(sm[d]);
        float a[4], b[4];
        #pragma unroll
        for (int k = 0; k < 4; k++) {
            float2 p = smr[t + 128 * k];
            a[k] = p.x;
            b[k] = p.y;
        }

        // strides 256, 512 (butterflies over k)
        bf(a[0], a[1]); bf(a[2], a[3]); bf(b[0], b[1]); bf(b[2], b[3]);
        bf(a[0], a[2]); bf(a[1], a[3]); bf(b[0], b[2]); bf(b[1], b[3]);

        // scaled, interleaved (real, 0) streaming stores; fully coalesced
        if (r0 + d < nrows) {
            float4* ob = yout + (size_t)(r0 + d) * (2 * DIMN / 4);
            #pragma unroll
            for (int k = 0; k < 4; k++) {
                __stcs(ob + t + 128 * k, make_float4(a[k] * s, 0.0f, b[k] * s, 0.0f));
            }
        }
    }
}

extern "C" void kernel_launch(void* const* d_in, const int* in_sizes, int n_in,
                              void* d_out, int out_size)
{
    const float* x = (const float*)d_in[0];   // [B, S, 1024] fp32
    // d_in[1] is H; unused — the transform is computed directly.
    float* out = (float*)d_out;               // [B, S, 1024, 2] fp32

    const int nrows = in_sizes[0] / DIMN;     // 16384
    const int grid  = (nrows + DEPTH - 1) / DEPTH;

    fwht_kernel<<<grid, TPR>>>((const float4*)x, (float4*)out, nrows);
}